// round 14
// baseline (speedup 1.0000x reference)
#include <cuda_runtime.h>
#include <cuda_fp16.h>
#include <cstdint>

// ---------------- problem constants ----------------
#define SPATIAL   3136
#define TOTAL_N   100352
#define BM        64
#define NCTA      1568                // TOTAL_N / BM
#define KC        32
#define NSTG      16                  // 512 / 32
#define ASTRIDE   40                  // padded floats per A smem row
#define BSTRH     48                  // padded halves per B smem row
#define ABYTES    (64 * ASTRIDE * 4)      // 10240
#define BBYTES    (512 * BSTRH * 2)       // 49152
#define STAGEB    (ABYTES + BBYTES)       // 59392
#define TS_STRIDE 520
#define SST_OFF   133120              // 64*520*4
#define SST_STR   68
#define BIAS_OFF  202752              // SST_OFF + 256*68*4
#define SMEM_BYTES 204800
#define TOTAL_OUT (32 * 512 * SPATIAL)

// ---------------- device scratch ----------------
__device__ __half g_wph[512 * 512];        // (W + I) fp16, k-interleaved per 16-chunk
__device__ __half g_sTh[256u * 100352u];   // s channel-major [256][N], fp16
__device__ float g_part[512 * NCTA];
__device__ float g_scale[512];
__device__ float g_shift[512];

// ---------------- helpers ----------------
union F4U { float4 v; unsigned long long u[2]; float f[4]; };

__device__ __forceinline__ uint32_t smem_u32(const void* p) {
    uint32_t a;
    asm("{ .reg .u64 t; cvta.to.shared.u64 t, %1; cvt.u32.u64 %0, t; }" : "=r"(a) : "l"(p));
    return a;
}
__device__ __forceinline__ void cp4(uint32_t dst, const void* src) {
    asm volatile("cp.async.ca.shared.global [%0], [%1], 4;" :: "r"(dst), "l"(src));
}
__device__ __forceinline__ void cp16(uint32_t dst, const void* src) {
    asm volatile("cp.async.cg.shared.global [%0], [%1], 16;" :: "r"(dst), "l"(src));
}
#define CP_COMMIT() asm volatile("cp.async.commit_group;" ::: "memory")
#define CP_WAIT1()  asm volatile("cp.async.wait_group 1;" ::: "memory")
#define CP_WAIT0()  asm volatile("cp.async.wait_group 0;" ::: "memory")

__device__ __forceinline__ uint32_t pack_f2h(float lo, float hi) {
    __half2 h = __floats2half2_rn(lo, hi);     // .x (low bits) = lo
    return *reinterpret_cast<uint32_t*>(&h);
}

// D(16x8) += A(16x16,row) * B(16x8,col) ; f16 inputs, f32 accum
__device__ __forceinline__ void mma16(float* c, const uint32_t* a, const uint32_t* b) {
    asm volatile("mma.sync.aligned.m16n8k16.row.col.f32.f16.f16.f32 "
        "{%0,%1,%2,%3}, {%4,%5,%6,%7}, {%8,%9}, {%0,%1,%2,%3};"
        : "+f"(c[0]), "+f"(c[1]), "+f"(c[2]), "+f"(c[3])
        : "r"(a[0]), "r"(a[1]), "r"(a[2]), "r"(a[3]), "r"(b[0]), "r"(b[1]));
}

__device__ __forceinline__ unsigned long long pack2(float lo, float hi) {
    unsigned long long r;
    asm("mov.b64 %0, {%1, %2};" : "=l"(r) : "f"(lo), "f"(hi));
    return r;
}
__device__ __forceinline__ void unpack2(unsigned long long v, float& lo, float& hi) {
    asm("mov.b64 {%0, %1}, %2;" : "=f"(lo), "=f"(hi) : "l"(v));
}
__device__ __forceinline__ void fma2(unsigned long long& d, unsigned long long a, unsigned long long b) {
    asm("fma.rn.f32x2 %0, %1, %2, %3;" : "=l"(d) : "l"(a), "l"(b), "l"(d));
}

// accurate fast tanh: 1 - 2/(exp(2x)+1)  (abs err ~1e-7)
__device__ __forceinline__ float tanh_fast(float x) {
    float e;
    asm("ex2.approx.f32 %0, %1;" : "=f"(e) : "f"(x * 2.8853900817779268f));
    float r;
    asm("rcp.approx.f32 %0, %1;" : "=f"(r) : "f"(e + 1.0f));
    return fmaf(-2.0f, r, 1.0f);
}

// =====================================================================
// K0: g_wph = fp16(W + I), k-interleaved within each k16 block:
// order [0,1,8,9, 2,3,10,11, 4,5,12,13, 6,7,14,15]
// =====================================================================
__global__ void k0_prep(const float* __restrict__ fcw) {
    int i = blockIdx.x * 256 + threadIdx.x;
    if (i < 512 * 512) {
        int n = i >> 9, k = i & 511;
        float v = fcw[i] + (n == k ? 1.0f : 0.0f);
        int kk = k & 15;
        int pos = (k & ~15) + ((kk & 7) >> 1) * 4 + (kk & 1) + (((kk >> 3) & 1) << 1);
        g_wph[n * 512 + pos] = __float2half_rn(v);
    }
}

// =====================================================================
// K1: fp16 mma.sync GEMM (t = x@(W+I)^T + b) -> symmetric bilinear -> tanh
//     -> s (L2 evict_last) + BN partials. grid=1568, block=256 (2m x 4n warps)
// =====================================================================
__global__ void __launch_bounds__(256, 1)
k1_gemm_bilinear(const float* __restrict__ x, const float* __restrict__ fcb)
{
    extern __shared__ char sm[];
    float* smf = (float*)sm;
    const uint32_t smb = smem_u32(sm);
    const int tid = threadIdx.x;
    const int lid = tid & 31;
    const int wid = tid >> 5;
    const int wm = wid >> 2;            // 0..1
    const int wn = wid & 3;             // 0..3
    const int g  = lid >> 2;            // 0..7
    const int t4 = lid & 3;             // 0..3
    const int cta = blockIdx.x;
    const int n0 = cta * BM;

    // bias -> smem (region disjoint from stage buffers)
    smf[BIAS_OFF / 4 + tid] = fcb[tid];
    smf[BIAS_OFF / 4 + 256 + tid] = fcb[256 + tid];

    // ---- A loader coords ----
    const int klo = tid >> 6;           // 0..3
    const int ar = tid & 63;
    const int an = n0 + ar;
    const int ab_ = an / SPATIAL;
    const float* aptr = x + (size_t)ab_ * (512 * SPATIAL) + (an - ab_ * SPATIAL);

    auto loadA = [&](int kt, uint32_t st) {
        #pragma unroll
        for (int j = 0; j < 8; ++j)
            cp4(smb + st + (uint32_t)(ar * ASTRIDE + klo + 4 * j) * 4,
                aptr + (size_t)(kt * KC + klo + 4 * j) * SPATIAL);
    };
    auto loadB = [&](int kt, uint32_t st) {
        #pragma unroll
        for (int i = 0; i < 8; ++i) {
            int idx = i * 256 + tid;
            int n = idx >> 2, ch = idx & 3;
            cp16(smb + st + ABYTES + (uint32_t)(n * BSTRH * 2 + ch * 16),
                 g_wph + (size_t)n * 512 + kt * KC + ch * 8);
        }
    };

    loadA(0, 0); loadB(0, 0); CP_COMMIT();
    loadA(1, STAGEB); loadB(1, STAGEB); CP_COMMIT();

    float acc[2][16][4];
    #pragma unroll
    for (int a = 0; a < 2; ++a)
        #pragma unroll
        for (int b = 0; b < 16; ++b)
            #pragma unroll
            for (int c = 0; c < 4; ++c) acc[a][b][c] = 0.0f;

    for (int kt = 0; kt < NSTG; ++kt) {
        if (kt == NSTG - 1) { CP_WAIT0(); } else { CP_WAIT1(); }
        __syncthreads();
        const uint32_t stb = (kt & 1) * STAGEB;
        const float* As = (const float*)(sm + stb);
        const __half* Bs = (const __half*)(sm + stb + ABYTES);

        // A fragments (fp32 smem -> fp16 regs)
        uint32_t aa[2][2][4];
        #pragma unroll
        for (int mt = 0; mt < 2; ++mt) {
            const int r0 = wm * 32 + mt * 16 + g;
            #pragma unroll
            for (int ks = 0; ks < 2; ++ks) {
                const int c0 = ks * 16 + 2 * t4;
                float2 v00 = *(const float2*)(As + r0 * ASTRIDE + c0);
                float2 v10 = *(const float2*)(As + (r0 + 8) * ASTRIDE + c0);
                float2 v01 = *(const float2*)(As + r0 * ASTRIDE + c0 + 8);
                float2 v11 = *(const float2*)(As + (r0 + 8) * ASTRIDE + c0 + 8);
                aa[mt][ks][0] = pack_f2h(v00.x, v00.y);
                aa[mt][ks][1] = pack_f2h(v10.x, v10.y);
                aa[mt][ks][2] = pack_f2h(v01.x, v01.y);
                aa[mt][ks][3] = pack_f2h(v11.x, v11.y);
            }
        }
        #pragma unroll
        for (int ks = 0; ks < 2; ++ks) {
            uint32_t bf[16][2];
            #pragma unroll
            for (int nt = 0; nt < 16; ++nt) {
                uint2 bv = *(const uint2*)(Bs + (wn * 128 + nt * 8 + g) * BSTRH
                                              + ks * 16 + 4 * t4);
                bf[nt][0] = bv.x; bf[nt][1] = bv.y;
            }
            #pragma unroll
            for (int nt = 0; nt < 16; ++nt) {
                mma16(acc[0][nt], aa[0][ks], bf[nt]);
                mma16(acc[1][nt], aa[1][ks], bf[nt]);
            }
        }
        __syncthreads();
        if (kt + 2 < NSTG) {
            loadA(kt + 2, stb);
            loadB(kt + 2, stb);
            CP_COMMIT();
        }
    }

    // ---- write t' (+bias) to smem staging [64][520] ----
    float* ts = smf;
    const float* bias = smf + BIAS_OFF / 4;
    #pragma unroll
    for (int mt = 0; mt < 2; ++mt) {
        const int r = wm * 32 + mt * 16 + g;
        #pragma unroll
        for (int nt = 0; nt < 16; ++nt) {
            const int n = wn * 128 + nt * 8 + t4 * 2;
            const float b0 = bias[n], b1 = bias[n + 1];
            *(float2*)(ts + r * TS_STRIDE + n) =
                make_float2(acc[mt][nt][0] + b0, acc[mt][nt][1] + b1);
            *(float2*)(ts + (r + 8) * TS_STRIDE + n) =
                make_float2(acc[mt][nt][2] + b0, acc[mt][nt][3] + b1);
        }
    }
    __syncthreads();

    // ---- symmetric bilinear: s[p][q] = tanh( dot/32 ), only q >= (p&~1),
    //      mirrored to (q,p). Warp-uniform pp = wid>>1, row = (wid&1)*32+lid.
    float* sst = smf + SST_OFF / 4;
    {
        const int pp = wid >> 1;            // 0..3, uniform per warp
        const int r  = (wid & 1) * 32 + lid;
        const float* trow = ts + r * TS_STRIDE;

        if (pp < 2) {
            // variant A: p = pp + 4h, j0 = {0,2,4,6}, pairs {8,6,4,2} = 20
            unsigned long long sa[20];
            #pragma unroll
            for (int e = 0; e < 20; ++e) sa[e] = 0ull;
            for (int gg = 0; gg < 32; ++gg) {
                F4U q0, q1, q2, q3;
                q0.v = *(const float4*)(trow + gg * 16);
                q1.v = *(const float4*)(trow + gg * 16 + 4);
                q2.v = *(const float4*)(trow + gg * 16 + 8);
                q3.v = *(const float4*)(trow + gg * 16 + 12);
                unsigned long long pv[8] = {
                    q0.u[0], q0.u[1], q1.u[0], q1.u[1],
                    q2.u[0], q2.u[1], q3.u[0], q3.u[1] };
                float tp0 = (pp == 0) ? q0.f[0] : q0.f[1];
                float tp1 = (pp == 0) ? q1.f[0] : q1.f[1];
                float tp2 = (pp == 0) ? q2.f[0] : q2.f[1];
                float tp3 = (pp == 0) ? q3.f[0] : q3.f[1];
                unsigned long long t0 = pack2(tp0, tp0), t1 = pack2(tp1, tp1);
                unsigned long long t2 = pack2(tp2, tp2), t3 = pack2(tp3, tp3);
                fma2(sa[0], t0, pv[0]); fma2(sa[1], t0, pv[1]);
                fma2(sa[2], t0, pv[2]); fma2(sa[3], t0, pv[3]);
                fma2(sa[4], t0, pv[4]); fma2(sa[5], t0, pv[5]);
                fma2(sa[6], t0, pv[6]); fma2(sa[7], t0, pv[7]);
                fma2(sa[8], t1, pv[2]); fma2(sa[9], t1, pv[3]);
                fma2(sa[10], t1, pv[4]); fma2(sa[11], t1, pv[5]);
                fma2(sa[12], t1, pv[6]); fma2(sa[13], t1, pv[7]);
                fma2(sa[14], t2, pv[4]); fma2(sa[15], t2, pv[5]);
                fma2(sa[16], t2, pv[6]); fma2(sa[17], t2, pv[7]);
                fma2(sa[18], t3, pv[6]); fma2(sa[19], t3, pv[7]);
            }
            const int base[4] = {0, 8, 14, 18};
            const int j0h[4] = {0, 2, 4, 6};
            #pragma unroll
            for (int h = 0; h < 4; ++h) {
                const int p = pp + 4 * h;
                #pragma unroll
                for (int e = 0; e < 8; ++e) {
                    if (e + j0h[h] >= 8) break;
                    const int q = 2 * (j0h[h] + e);
                    float lo, hi;
                    unpack2(sa[base[h] + e], lo, hi);
                    float vlo = __half2float(__float2half_rn(tanh_fast(lo * 0.03125f)));
                    float vhi = __half2float(__float2half_rn(tanh_fast(hi * 0.03125f)));
                    sst[(p * 16 + q) * SST_STR + r]       = vlo;
                    sst[(p * 16 + q + 1) * SST_STR + r]   = vhi;
                    sst[(q * 16 + p) * SST_STR + r]       = vlo;
                    sst[((q + 1) * 16 + p) * SST_STR + r] = vhi;
                }
            }
        } else {
            // variant B: p = pp + 4h, j0 = {1,3,5,7}, pairs {7,5,3,1} = 16
            unsigned long long sa[16];
            #pragma unroll
            for (int e = 0; e < 16; ++e) sa[e] = 0ull;
            for (int gg = 0; gg < 32; ++gg) {
                F4U q0, q1, q2, q3;
                q0.v = *(const float4*)(trow + gg * 16);
                q1.v = *(const float4*)(trow + gg * 16 + 4);
                q2.v = *(const float4*)(trow + gg * 16 + 8);
                q3.v = *(const float4*)(trow + gg * 16 + 12);
                unsigned long long pv[8] = {
                    q0.u[0], q0.u[1], q1.u[0], q1.u[1],
                    q2.u[0], q2.u[1], q3.u[0], q3.u[1] };
                float tp0 = (pp == 2) ? q0.f[2] : q0.f[3];
                float tp1 = (pp == 2) ? q1.f[2] : q1.f[3];
                float tp2 = (pp == 2) ? q2.f[2] : q2.f[3];
                float tp3 = (pp == 2) ? q3.f[2] : q3.f[3];
                unsigned long long t0 = pack2(tp0, tp0), t1 = pack2(tp1, tp1);
                unsigned long long t2 = pack2(tp2, tp2), t3 = pack2(tp3, tp3);
                fma2(sa[0], t0, pv[1]); fma2(sa[1], t0, pv[2]);
                fma2(sa[2], t0, pv[3]); fma2(sa[3], t0, pv[4]);
                fma2(sa[4], t0, pv[5]); fma2(sa[5], t0, pv[6]);
                fma2(sa[6], t0, pv[7]);
                fma2(sa[7], t1, pv[3]); fma2(sa[8], t1, pv[4]);
                fma2(sa[9], t1, pv[5]); fma2(sa[10], t1, pv[6]);
                fma2(sa[11], t1, pv[7]);
                fma2(sa[12], t2, pv[5]); fma2(sa[13], t2, pv[6]);
                fma2(sa[14], t2, pv[7]);
                fma2(sa[15], t3, pv[7]);
            }
            const int base[4] = {0, 7, 12, 15};
            const int j0h[4] = {1, 3, 5, 7};
            #pragma unroll
            for (int h = 0; h < 4; ++h) {
                const int p = pp + 4 * h;
                #pragma unroll
                for (int e = 0; e < 7; ++e) {
                    if (e + j0h[h] >= 8) break;
                    const int q = 2 * (j0h[h] + e);
                    float lo, hi;
                    unpack2(sa[base[h] + e], lo, hi);
                    float vlo = __half2float(__float2half_rn(tanh_fast(lo * 0.03125f)));
                    float vhi = __half2float(__float2half_rn(tanh_fast(hi * 0.03125f)));
                    sst[(p * 16 + q) * SST_STR + r]       = vlo;
                    sst[(p * 16 + q + 1) * SST_STR + r]   = vhi;
                    sst[(q * 16 + p) * SST_STR + r]       = vlo;
                    sst[((q + 1) * 16 + p) * SST_STR + r] = vhi;
                }
            }
        }
    }
    __syncthreads();

    // ---- BN partials (thread = channel) ----
    {
        float s = 0.0f, q = 0.0f;
        const float* row = sst + tid * SST_STR;
        #pragma unroll
        for (int m4 = 0; m4 < 16; ++m4) {
            float4 v = *(const float4*)(row + m4 * 4);
            s += (v.x + v.y) + (v.z + v.w);
            q += fmaf(v.x, v.x, fmaf(v.y, v.y, fmaf(v.z, v.z, v.w * v.w)));
        }
        g_part[tid * NCTA + cta] = s;
        g_part[(tid + 256) * NCTA + cta] = q;
    }
    // ---- coalesced channel-major s write (fp16), L2 evict_last ----
    {
        unsigned long long pol;
        asm("createpolicy.fractional.L2::evict_last.b64 %0, 1.0;" : "=l"(pol));
        #pragma unroll
        for (int it = 0; it < 16; ++it) {
            int idx = it * 256 + tid;
            int ch = idx >> 4, c4 = idx & 15;
            float4 v = *(const float4*)(sst + ch * SST_STR + c4 * 4);
            __half2 h0 = __floats2half2_rn(v.x, v.y);
            __half2 h1 = __floats2half2_rn(v.z, v.w);
            uint32_t o0 = *reinterpret_cast<uint32_t*>(&h0);
            uint32_t o1 = *reinterpret_cast<uint32_t*>(&h1);
            __half* gp = g_sTh + (size_t)ch * TOTAL_N + n0 + c4 * 4;
            asm volatile("st.global.L2::cache_hint.v2.b32 [%0], {%1,%2}, %3;"
                         :: "l"(gp), "r"(o0), "r"(o1), "l"(pol) : "memory");
        }
    }
}

// =====================================================================
// K2: fold BN stats -> per-channel scale/shift (fp64 reduction)
// =====================================================================
__global__ void k2_stats(const float* __restrict__ gamma,
                         const float* __restrict__ beta)
{
    __shared__ double rs[256], rq[256];
    const int c = blockIdx.x;
    const int c2 = c >> 1;
    const int tid = threadIdx.x;
    double s = 0.0, q = 0.0;
    for (int i = tid; i < NCTA; i += 256) {
        s += (double)g_part[c2 * NCTA + i];
        q += (double)g_part[(c2 + 256) * NCTA + i];
    }
    rs[tid] = s; rq[tid] = q;
    __syncthreads();
    for (int off = 128; off > 0; off >>= 1) {
        if (tid < off) { rs[tid] += rs[tid + off]; rq[tid] += rq[tid + off]; }
        __syncthreads();
    }
    if (tid == 0) {
        const double inv_n = 1.0 / (double)TOTAL_N;
        const double mean = rs[0] * inv_n;
        const double var = rq[0] * inv_n - mean * mean;
        const double rstd = 1.0 / sqrt(var + 1e-5);
        const double gm = (double)gamma[c];
        g_scale[c] = (float)(gm * rstd);
        g_shift[c] = (float)((double)beta[c] - mean * rstd * gm);
    }
}

// =====================================================================
// K3: out = x + s[c>>1]*scale[c] + shift[c]
// One thread = one channel-PAIR x 8 spatial (16 outputs): one uint4 s load,
// 4 x float4 streaming loads, 4 streaming stores. Deeper MLP.
// =====================================================================
__global__ void k3_out(const float* __restrict__ x, float* __restrict__ out)
{
    const int idx = blockIdx.x * 256 + threadIdx.x;
    if (idx >= TOTAL_OUT / 16) return;         // 3,211,264 threads
    const int sp8 = idx % 392;                 // SPATIAL/8
    const int rest = idx / 392;
    const int cp = rest & 255;                 // s channel (c>>1)
    const int b = rest >> 8;
    const int c0 = cp * 2;

    // one 16B s load = 8 halves, feeds both output channels x 8 spatial
    uint4 raw = __ldcs((const uint4*)(g_sTh + (size_t)cp * TOTAL_N + b * SPATIAL + sp8 * 8));
    float2 f0 = __half22float2(*reinterpret_cast<__half2*>(&raw.x));
    float2 f1 = __half22float2(*reinterpret_cast<__half2*>(&raw.y));
    float2 f2 = __half22float2(*reinterpret_cast<__half2*>(&raw.z));
    float2 f3 = __half22float2(*reinterpret_cast<__half2*>(&raw.w));
    float sv[8] = { f0.x, f0.y, f1.x, f1.y, f2.x, f2.y, f3.x, f3.y };

    const float* xp = x + ((size_t)(b * 512 + c0)) * SPATIAL + sp8 * 8;
    float4 xv00 = __ldcs((const float4*)xp);
    float4 xv01 = __ldcs((const float4*)(xp + 4));
    float4 xv10 = __ldcs((const float4*)(xp + SPATIAL));
    float4 xv11 = __ldcs((const float4*)(xp + SPATIAL + 4));

    const float sc0 = g_scale[c0],     sh0 = g_shift[c0];
    const float sc1 = g_scale[c0 + 1], sh1 = g_shift[c0 + 1];

    float4 o00, o01, o10, o11;
    o00.x = xv00.x + fmaf(sv[0], sc0, sh0);
    o00.y = xv00.y + fmaf(sv[1], sc0, sh0);
    o00.z = xv00.z + fmaf(sv[2], sc0, sh0);
    o00.w = xv00.w + fmaf(sv[3], sc0, sh0);
    o01.x = xv01.x + fmaf(sv[4], sc0, sh0);
    o01.y = xv01.y + fmaf(sv[5], sc0, sh0);
    o01.z = xv01.z + fmaf(sv[6], sc0, sh0);
    o01.w = xv01.w + fmaf(sv[7], sc0, sh0);
    o10.x = xv10.x + fmaf(sv[0], sc1, sh1);
    o10.y = xv10.y + fmaf(sv[1], sc1, sh1);
    o10.z = xv10.z + fmaf(sv[2], sc1, sh1);
    o10.w = xv10.w + fmaf(sv[3], sc1, sh1);
    o11.x = xv11.x + fmaf(sv[4], sc1, sh1);
    o11.y = xv11.y + fmaf(sv[5], sc1, sh1);
    o11.z = xv11.z + fmaf(sv[6], sc1, sh1);
    o11.w = xv11.w + fmaf(sv[7], sc1, sh1);

    float* op = out + ((size_t)(b * 512 + c0)) * SPATIAL + sp8 * 8;
    __stcs((float4*)op, o00);
    __stcs((float4*)(op + 4), o01);
    __stcs((float4*)(op + SPATIAL), o10);
    __stcs((float4*)(op + SPATIAL + 4), o11);
}

// =====================================================================
extern "C" void kernel_launch(void* const* d_in, const int* in_sizes, int n_in,
                              void* d_out, int out_size)
{
    const float* x     = (const float*)d_in[0];
    const float* fcw   = (const float*)d_in[1];
    const float* fcb   = (const float*)d_in[2];
    const float* gamma = (const float*)d_in[3];
    const float* beta  = (const float*)d_in[4];
    float* out = (float*)d_out;

    cudaFuncSetAttribute(k1_gemm_bilinear,
                         cudaFuncAttributeMaxDynamicSharedMemorySize, SMEM_BYTES);

    k0_prep<<<1024, 256>>>(fcw);
    k1_gemm_bilinear<<<NCTA, 256, SMEM_BYTES>>>(x, fcb);
    k2_stats<<<512, 256>>>(gamma, beta);
    k3_out<<<(TOTAL_OUT / 16 + 255) / 256, 256>>>(x, out);
}

// round 15
// speedup vs baseline: 1.0118x; 1.0118x over previous
#include <cuda_runtime.h>
#include <cuda_fp16.h>
#include <cstdint>

// ---------------- problem constants ----------------
#define SPATIAL   3136
#define TOTAL_N   100352
#define BM        64
#define NCTA      1568                // TOTAL_N / BM
#define KC        32
#define NSTG      16                  // 512 / 32
#define ASTRIDE   40                  // padded floats per A smem row
#define BSTRH     48                  // padded halves per B smem row
#define ABYTES    (64 * ASTRIDE * 4)      // 10240
#define BBYTES    (512 * BSTRH * 2)       // 49152
#define STAGEB    (ABYTES + BBYTES)       // 59392
#define TS_STRIDE 520
#define SST_OFF   133120              // 64*520*4
#define SST_STR   68
#define BIAS_OFF  202752              // SST_OFF + 256*68*4
#define SMEM_BYTES 204800
#define TOTAL_OUT (32 * 512 * SPATIAL)

// ---------------- device scratch ----------------
__device__ __half g_wph[512 * 512];        // (W + I) fp16, k-interleaved per 16-chunk
__device__ __half g_sTh[256u * 100352u];   // s channel-major [256][N], fp16
__device__ float g_part[512 * NCTA];
__device__ float g_scale[512];
__device__ float g_shift[512];

// ---------------- helpers ----------------
union F4U { float4 v; unsigned long long u[2]; float f[4]; };

__device__ __forceinline__ uint32_t smem_u32(const void* p) {
    uint32_t a;
    asm("{ .reg .u64 t; cvta.to.shared.u64 t, %1; cvt.u32.u64 %0, t; }" : "=r"(a) : "l"(p));
    return a;
}
__device__ __forceinline__ void cp4(uint32_t dst, const void* src) {
    asm volatile("cp.async.ca.shared.global [%0], [%1], 4;" :: "r"(dst), "l"(src));
}
__device__ __forceinline__ void cp16(uint32_t dst, const void* src) {
    asm volatile("cp.async.cg.shared.global [%0], [%1], 16;" :: "r"(dst), "l"(src));
}
#define CP_COMMIT() asm volatile("cp.async.commit_group;" ::: "memory")
#define CP_WAIT1()  asm volatile("cp.async.wait_group 1;" ::: "memory")
#define CP_WAIT0()  asm volatile("cp.async.wait_group 0;" ::: "memory")

__device__ __forceinline__ uint32_t pack_f2h(float lo, float hi) {
    __half2 h = __floats2half2_rn(lo, hi);     // .x (low bits) = lo
    return *reinterpret_cast<uint32_t*>(&h);
}

// D(16x8) += A(16x16,row) * B(16x8,col) ; f16 inputs, f32 accum
__device__ __forceinline__ void mma16(float* c, const uint32_t* a, const uint32_t* b) {
    asm volatile("mma.sync.aligned.m16n8k16.row.col.f32.f16.f16.f32 "
        "{%0,%1,%2,%3}, {%4,%5,%6,%7}, {%8,%9}, {%0,%1,%2,%3};"
        : "+f"(c[0]), "+f"(c[1]), "+f"(c[2]), "+f"(c[3])
        : "r"(a[0]), "r"(a[1]), "r"(a[2]), "r"(a[3]), "r"(b[0]), "r"(b[1]));
}

__device__ __forceinline__ unsigned long long pack2(float lo, float hi) {
    unsigned long long r;
    asm("mov.b64 %0, {%1, %2};" : "=l"(r) : "f"(lo), "f"(hi));
    return r;
}
__device__ __forceinline__ void unpack2(unsigned long long v, float& lo, float& hi) {
    asm("mov.b64 {%0, %1}, %2;" : "=f"(lo), "=f"(hi) : "l"(v));
}
__device__ __forceinline__ void fma2(unsigned long long& d, unsigned long long a, unsigned long long b) {
    asm("fma.rn.f32x2 %0, %1, %2, %3;" : "=l"(d) : "l"(a), "l"(b), "l"(d));
}

// accurate fast tanh: 1 - 2/(exp(2x)+1)  (abs err ~1e-7)
__device__ __forceinline__ float tanh_fast(float x) {
    float e;
    asm("ex2.approx.f32 %0, %1;" : "=f"(e) : "f"(x * 2.8853900817779268f));
    float r;
    asm("rcp.approx.f32 %0, %1;" : "=f"(r) : "f"(e + 1.0f));
    return fmaf(-2.0f, r, 1.0f);
}

// =====================================================================
// K0: g_wph = fp16(W + I), k-interleaved within each k16 block:
// order [0,1,8,9, 2,3,10,11, 4,5,12,13, 6,7,14,15]
// =====================================================================
__global__ void k0_prep(const float* __restrict__ fcw) {
    int i = blockIdx.x * 256 + threadIdx.x;
    if (i < 512 * 512) {
        int n = i >> 9, k = i & 511;
        float v = fcw[i] + (n == k ? 1.0f : 0.0f);
        int kk = k & 15;
        int pos = (k & ~15) + ((kk & 7) >> 1) * 4 + (kk & 1) + (((kk >> 3) & 1) << 1);
        g_wph[n * 512 + pos] = __float2half_rn(v);
    }
}

// =====================================================================
// K1: fp16 mma.sync GEMM (t = x@(W+I)^T + b) -> symmetric bilinear -> tanh
//     -> s (L2 evict_last) + BN partials. grid=1568, block=256 (2m x 4n warps)
// =====================================================================
__global__ void __launch_bounds__(256, 1)
k1_gemm_bilinear(const float* __restrict__ x, const float* __restrict__ fcb)
{
    extern __shared__ char sm[];
    float* smf = (float*)sm;
    const uint32_t smb = smem_u32(sm);
    const int tid = threadIdx.x;
    const int lid = tid & 31;
    const int wid = tid >> 5;
    const int wm = wid >> 2;            // 0..1
    const int wn = wid & 3;             // 0..3
    const int g  = lid >> 2;            // 0..7
    const int t4 = lid & 3;             // 0..3
    const int cta = blockIdx.x;
    const int n0 = cta * BM;

    // bias -> smem (region disjoint from stage buffers)
    smf[BIAS_OFF / 4 + tid] = fcb[tid];
    smf[BIAS_OFF / 4 + 256 + tid] = fcb[256 + tid];

    // ---- A loader coords ----
    const int klo = tid >> 6;           // 0..3
    const int ar = tid & 63;
    const int an = n0 + ar;
    const int ab_ = an / SPATIAL;
    const float* aptr = x + (size_t)ab_ * (512 * SPATIAL) + (an - ab_ * SPATIAL);

    auto loadA = [&](int kt, uint32_t st) {
        #pragma unroll
        for (int j = 0; j < 8; ++j)
            cp4(smb + st + (uint32_t)(ar * ASTRIDE + klo + 4 * j) * 4,
                aptr + (size_t)(kt * KC + klo + 4 * j) * SPATIAL);
    };
    auto loadB = [&](int kt, uint32_t st) {
        #pragma unroll
        for (int i = 0; i < 8; ++i) {
            int idx = i * 256 + tid;
            int n = idx >> 2, ch = idx & 3;
            cp16(smb + st + ABYTES + (uint32_t)(n * BSTRH * 2 + ch * 16),
                 g_wph + (size_t)n * 512 + kt * KC + ch * 8);
        }
    };

    loadA(0, 0); loadB(0, 0); CP_COMMIT();
    loadA(1, STAGEB); loadB(1, STAGEB); CP_COMMIT();

    float acc[2][16][4];
    #pragma unroll
    for (int a = 0; a < 2; ++a)
        #pragma unroll
        for (int b = 0; b < 16; ++b)
            #pragma unroll
            for (int c = 0; c < 4; ++c) acc[a][b][c] = 0.0f;

    for (int kt = 0; kt < NSTG; ++kt) {
        if (kt == NSTG - 1) { CP_WAIT0(); } else { CP_WAIT1(); }
        __syncthreads();
        const uint32_t stb = (kt & 1) * STAGEB;
        const float* As = (const float*)(sm + stb);
        const __half* Bs = (const __half*)(sm + stb + ABYTES);

        // A fragments (fp32 smem -> fp16 regs)
        uint32_t aa[2][2][4];
        #pragma unroll
        for (int mt = 0; mt < 2; ++mt) {
            const int r0 = wm * 32 + mt * 16 + g;
            #pragma unroll
            for (int ks = 0; ks < 2; ++ks) {
                const int c0 = ks * 16 + 2 * t4;
                float2 v00 = *(const float2*)(As + r0 * ASTRIDE + c0);
                float2 v10 = *(const float2*)(As + (r0 + 8) * ASTRIDE + c0);
                float2 v01 = *(const float2*)(As + r0 * ASTRIDE + c0 + 8);
                float2 v11 = *(const float2*)(As + (r0 + 8) * ASTRIDE + c0 + 8);
                aa[mt][ks][0] = pack_f2h(v00.x, v00.y);
                aa[mt][ks][1] = pack_f2h(v10.x, v10.y);
                aa[mt][ks][2] = pack_f2h(v01.x, v01.y);
                aa[mt][ks][3] = pack_f2h(v11.x, v11.y);
            }
        }
        #pragma unroll
        for (int ks = 0; ks < 2; ++ks) {
            uint32_t bf[16][2];
            #pragma unroll
            for (int nt = 0; nt < 16; ++nt) {
                uint2 bv = *(const uint2*)(Bs + (wn * 128 + nt * 8 + g) * BSTRH
                                              + ks * 16 + 4 * t4);
                bf[nt][0] = bv.x; bf[nt][1] = bv.y;
            }
            #pragma unroll
            for (int nt = 0; nt < 16; ++nt) {
                mma16(acc[0][nt], aa[0][ks], bf[nt]);
                mma16(acc[1][nt], aa[1][ks], bf[nt]);
            }
        }
        __syncthreads();
        if (kt + 2 < NSTG) {
            loadA(kt + 2, stb);
            loadB(kt + 2, stb);
            CP_COMMIT();
        }
    }

    // ---- write t' (+bias) to smem staging [64][520] ----
    float* ts = smf;
    const float* bias = smf + BIAS_OFF / 4;
    #pragma unroll
    for (int mt = 0; mt < 2; ++mt) {
        const int r = wm * 32 + mt * 16 + g;
        #pragma unroll
        for (int nt = 0; nt < 16; ++nt) {
            const int n = wn * 128 + nt * 8 + t4 * 2;
            const float b0 = bias[n], b1 = bias[n + 1];
            *(float2*)(ts + r * TS_STRIDE + n) =
                make_float2(acc[mt][nt][0] + b0, acc[mt][nt][1] + b1);
            *(float2*)(ts + (r + 8) * TS_STRIDE + n) =
                make_float2(acc[mt][nt][2] + b0, acc[mt][nt][3] + b1);
        }
    }
    __syncthreads();

    // ---- symmetric bilinear: s[p][q] = tanh( dot/32 ), only q >= (p&~1),
    //      mirrored to (q,p). Warp-uniform pp = wid>>1, row = (wid&1)*32+lid.
    float* sst = smf + SST_OFF / 4;
    {
        const int pp = wid >> 1;            // 0..3, uniform per warp
        const int r  = (wid & 1) * 32 + lid;
        const float* trow = ts + r * TS_STRIDE;

        if (pp < 2) {
            // variant A: p = pp + 4h, j0 = {0,2,4,6}, pairs {8,6,4,2} = 20
            unsigned long long sa[20];
            #pragma unroll
            for (int e = 0; e < 20; ++e) sa[e] = 0ull;
            for (int gg = 0; gg < 32; ++gg) {
                F4U q0, q1, q2, q3;
                q0.v = *(const float4*)(trow + gg * 16);
                q1.v = *(const float4*)(trow + gg * 16 + 4);
                q2.v = *(const float4*)(trow + gg * 16 + 8);
                q3.v = *(const float4*)(trow + gg * 16 + 12);
                unsigned long long pv[8] = {
                    q0.u[0], q0.u[1], q1.u[0], q1.u[1],
                    q2.u[0], q2.u[1], q3.u[0], q3.u[1] };
                float tp0 = (pp == 0) ? q0.f[0] : q0.f[1];
                float tp1 = (pp == 0) ? q1.f[0] : q1.f[1];
                float tp2 = (pp == 0) ? q2.f[0] : q2.f[1];
                float tp3 = (pp == 0) ? q3.f[0] : q3.f[1];
                unsigned long long t0 = pack2(tp0, tp0), t1 = pack2(tp1, tp1);
                unsigned long long t2 = pack2(tp2, tp2), t3 = pack2(tp3, tp3);
                fma2(sa[0], t0, pv[0]); fma2(sa[1], t0, pv[1]);
                fma2(sa[2], t0, pv[2]); fma2(sa[3], t0, pv[3]);
                fma2(sa[4], t0, pv[4]); fma2(sa[5], t0, pv[5]);
                fma2(sa[6], t0, pv[6]); fma2(sa[7], t0, pv[7]);
                fma2(sa[8], t1, pv[2]); fma2(sa[9], t1, pv[3]);
                fma2(sa[10], t1, pv[4]); fma2(sa[11], t1, pv[5]);
                fma2(sa[12], t1, pv[6]); fma2(sa[13], t1, pv[7]);
                fma2(sa[14], t2, pv[4]); fma2(sa[15], t2, pv[5]);
                fma2(sa[16], t2, pv[6]); fma2(sa[17], t2, pv[7]);
                fma2(sa[18], t3, pv[6]); fma2(sa[19], t3, pv[7]);
            }
            const int base[4] = {0, 8, 14, 18};
            const int j0h[4] = {0, 2, 4, 6};
            #pragma unroll
            for (int h = 0; h < 4; ++h) {
                const int p = pp + 4 * h;
                #pragma unroll
                for (int e = 0; e < 8; ++e) {
                    if (e + j0h[h] >= 8) break;
                    const int q = 2 * (j0h[h] + e);
                    float lo, hi;
                    unpack2(sa[base[h] + e], lo, hi);
                    float vlo = __half2float(__float2half_rn(tanh_fast(lo * 0.03125f)));
                    float vhi = __half2float(__float2half_rn(tanh_fast(hi * 0.03125f)));
                    sst[(p * 16 + q) * SST_STR + r]       = vlo;
                    sst[(p * 16 + q + 1) * SST_STR + r]   = vhi;
                    sst[(q * 16 + p) * SST_STR + r]       = vlo;
                    sst[((q + 1) * 16 + p) * SST_STR + r] = vhi;
                }
            }
        } else {
            // variant B: p = pp + 4h, j0 = {1,3,5,7}, pairs {7,5,3,1} = 16
            unsigned long long sa[16];
            #pragma unroll
            for (int e = 0; e < 16; ++e) sa[e] = 0ull;
            for (int gg = 0; gg < 32; ++gg) {
                F4U q0, q1, q2, q3;
                q0.v = *(const float4*)(trow + gg * 16);
                q1.v = *(const float4*)(trow + gg * 16 + 4);
                q2.v = *(const float4*)(trow + gg * 16 + 8);
                q3.v = *(const float4*)(trow + gg * 16 + 12);
                unsigned long long pv[8] = {
                    q0.u[0], q0.u[1], q1.u[0], q1.u[1],
                    q2.u[0], q2.u[1], q3.u[0], q3.u[1] };
                float tp0 = (pp == 2) ? q0.f[2] : q0.f[3];
                float tp1 = (pp == 2) ? q1.f[2] : q1.f[3];
                float tp2 = (pp == 2) ? q2.f[2] : q2.f[3];
                float tp3 = (pp == 2) ? q3.f[2] : q3.f[3];
                unsigned long long t0 = pack2(tp0, tp0), t1 = pack2(tp1, tp1);
                unsigned long long t2 = pack2(tp2, tp2), t3 = pack2(tp3, tp3);
                fma2(sa[0], t0, pv[1]); fma2(sa[1], t0, pv[2]);
                fma2(sa[2], t0, pv[3]); fma2(sa[3], t0, pv[4]);
                fma2(sa[4], t0, pv[5]); fma2(sa[5], t0, pv[6]);
                fma2(sa[6], t0, pv[7]);
                fma2(sa[7], t1, pv[3]); fma2(sa[8], t1, pv[4]);
                fma2(sa[9], t1, pv[5]); fma2(sa[10], t1, pv[6]);
                fma2(sa[11], t1, pv[7]);
                fma2(sa[12], t2, pv[5]); fma2(sa[13], t2, pv[6]);
                fma2(sa[14], t2, pv[7]);
                fma2(sa[15], t3, pv[7]);
            }
            const int base[4] = {0, 7, 12, 15};
            const int j0h[4] = {1, 3, 5, 7};
            #pragma unroll
            for (int h = 0; h < 4; ++h) {
                const int p = pp + 4 * h;
                #pragma unroll
                for (int e = 0; e < 7; ++e) {
                    if (e + j0h[h] >= 8) break;
                    const int q = 2 * (j0h[h] + e);
                    float lo, hi;
                    unpack2(sa[base[h] + e], lo, hi);
                    float vlo = __half2float(__float2half_rn(tanh_fast(lo * 0.03125f)));
                    float vhi = __half2float(__float2half_rn(tanh_fast(hi * 0.03125f)));
                    sst[(p * 16 + q) * SST_STR + r]       = vlo;
                    sst[(p * 16 + q + 1) * SST_STR + r]   = vhi;
                    sst[(q * 16 + p) * SST_STR + r]       = vlo;
                    sst[((q + 1) * 16 + p) * SST_STR + r] = vhi;
                }
            }
        }
    }
    __syncthreads();

    // ---- BN partials (thread = channel) ----
    {
        float s = 0.0f, q = 0.0f;
        const float* row = sst + tid * SST_STR;
        #pragma unroll
        for (int m4 = 0; m4 < 16; ++m4) {
            float4 v = *(const float4*)(row + m4 * 4);
            s += (v.x + v.y) + (v.z + v.w);
            q += fmaf(v.x, v.x, fmaf(v.y, v.y, fmaf(v.z, v.z, v.w * v.w)));
        }
        g_part[tid * NCTA + cta] = s;
        g_part[(tid + 256) * NCTA + cta] = q;
    }
    // ---- coalesced channel-major s write (fp16), L2 evict_last ----
    {
        unsigned long long pol;
        asm("createpolicy.fractional.L2::evict_last.b64 %0, 1.0;" : "=l"(pol));
        #pragma unroll
        for (int it = 0; it < 16; ++it) {
            int idx = it * 256 + tid;
            int ch = idx >> 4, c4 = idx & 15;
            float4 v = *(const float4*)(sst + ch * SST_STR + c4 * 4);
            __half2 h0 = __floats2half2_rn(v.x, v.y);
            __half2 h1 = __floats2half2_rn(v.z, v.w);
            uint32_t o0 = *reinterpret_cast<uint32_t*>(&h0);
            uint32_t o1 = *reinterpret_cast<uint32_t*>(&h1);
            __half* gp = g_sTh + (size_t)ch * TOTAL_N + n0 + c4 * 4;
            asm volatile("st.global.L2::cache_hint.v2.b32 [%0], {%1,%2}, %3;"
                         :: "l"(gp), "r"(o0), "r"(o1), "l"(pol) : "memory");
        }
    }
}

// =====================================================================
// K2: fold BN stats -> per-channel scale/shift (fp64 reduction)
// =====================================================================
__global__ void k2_stats(const float* __restrict__ gamma,
                         const float* __restrict__ beta)
{
    __shared__ double rs[256], rq[256];
    const int c = blockIdx.x;
    const int c2 = c >> 1;
    const int tid = threadIdx.x;
    double s = 0.0, q = 0.0;
    for (int i = tid; i < NCTA; i += 256) {
        s += (double)g_part[c2 * NCTA + i];
        q += (double)g_part[(c2 + 256) * NCTA + i];
    }
    rs[tid] = s; rq[tid] = q;
    __syncthreads();
    for (int off = 128; off > 0; off >>= 1) {
        if (tid < off) { rs[tid] += rs[tid + off]; rq[tid] += rq[tid + off]; }
        __syncthreads();
    }
    if (tid == 0) {
        const double inv_n = 1.0 / (double)TOTAL_N;
        const double mean = rs[0] * inv_n;
        const double var = rq[0] * inv_n - mean * mean;
        const double rstd = 1.0 / sqrt(var + 1e-5);
        const double gm = (double)gamma[c];
        g_scale[c] = (float)(gm * rstd);
        g_shift[c] = (float)((double)beta[c] - mean * rstd * gm);
    }
}

// =====================================================================
// K3: out = x + s[c>>1]*scale[c] + shift[c]
// One thread = one channel-PAIR (2c, 2c+1) x 4 spatial: s read once
// (streaming ld, hits the evict_last L2 lines), x streaming, out streaming.
// =====================================================================
__global__ void k3_out(const float* __restrict__ x, float* __restrict__ out)
{
    const int idx = blockIdx.x * 256 + threadIdx.x;
    if (idx >= TOTAL_OUT / 8) return;          // 6,422,528 threads
    const int sp4 = idx % 784;                 // SPATIAL/4
    const int rest = idx / 784;
    const int cp = rest & 255;                 // s channel (c>>1)
    const int b = rest >> 8;
    const int c0 = cp * 2;

    uint2 raw = __ldcs((const uint2*)(g_sTh + (size_t)cp * TOTAL_N + b * SPATIAL + sp4 * 4));
    __half2 h0 = *reinterpret_cast<__half2*>(&raw.x);
    __half2 h1 = *reinterpret_cast<__half2*>(&raw.y);
    float2 f0 = __half22float2(h0);
    float2 f1 = __half22float2(h1);

    const float* xp = x + ((size_t)(b * 512 + c0)) * SPATIAL + sp4 * 4;
    float4 xv0 = __ldcs((const float4*)xp);
    float4 xv1 = __ldcs((const float4*)(xp + SPATIAL));

    const float sc0 = g_scale[c0],     sh0 = g_shift[c0];
    const float sc1 = g_scale[c0 + 1], sh1 = g_shift[c0 + 1];

    float4 o0, o1;
    o0.x = xv0.x + fmaf(f0.x, sc0, sh0);
    o0.y = xv0.y + fmaf(f0.y, sc0, sh0);
    o0.z = xv0.z + fmaf(f1.x, sc0, sh0);
    o0.w = xv0.w + fmaf(f1.y, sc0, sh0);
    o1.x = xv1.x + fmaf(f0.x, sc1, sh1);
    o1.y = xv1.y + fmaf(f0.y, sc1, sh1);
    o1.z = xv1.z + fmaf(f1.x, sc1, sh1);
    o1.w = xv1.w + fmaf(f1.y, sc1, sh1);

    float* op = out + ((size_t)(b * 512 + c0)) * SPATIAL + sp4 * 4;
    __stcs((float4*)op, o0);
    __stcs((float4*)(op + SPATIAL), o1);
}

// =====================================================================
extern "C" void kernel_launch(void* const* d_in, const int* in_sizes, int n_in,
                              void* d_out, int out_size)
{
    const float* x     = (const float*)d_in[0];
    const float* fcw   = (const float*)d_in[1];
    const float* fcb   = (const float*)d_in[2];
    const float* gamma = (const float*)d_in[3];
    const float* beta  = (const float*)d_in[4];
    float* out = (float*)d_out;

    cudaFuncSetAttribute(k1_gemm_bilinear,
                         cudaFuncAttributeMaxDynamicSharedMemorySize, SMEM_BYTES);

    k0_prep<<<1024, 256>>>(fcw);
    k1_gemm_bilinear<<<NCTA, 256, SMEM_BYTES>>>(x, fcb);
    k2_stats<<<512, 256>>>(gamma, beta);
    k3_out<<<(TOTAL_OUT / 8 + 255) / 256, 256>>>(x, out);
}

// round 16
// speedup vs baseline: 1.0250x; 1.0130x over previous
#include <cuda_runtime.h>
#include <cuda_fp16.h>
#include <cstdint>

// ---------------- problem constants ----------------
#define SPATIAL   3136
#define TOTAL_N   100352
#define BM        64
#define NCTA      1568                // TOTAL_N / BM
#define KC        32
#define NSTG      16                  // 512 / 32
#define ASTRIDE   40                  // padded floats per A smem row
#define BSTRH     48                  // padded halves per B smem row
#define ABYTES    (64 * ASTRIDE * 4)      // 10240
#define BBYTES    (512 * BSTRH * 2)       // 49152
#define STAGEB    (ABYTES + BBYTES)       // 59392
#define TS_STRIDE 520
#define SST_OFF   133120              // 64*520*4
#define SST_STR   68
#define BIAS_OFF  202752              // SST_OFF + 256*68*4
#define SMEM_BYTES 204800
#define TOTAL_OUT (32 * 512 * SPATIAL)

// ---------------- device scratch ----------------
__device__ __half g_wph[512 * 512];        // (W + I) fp16, k-interleaved per 16-chunk
__device__ __half g_sTh[256u * 100352u];   // s channel-major [256][N], fp16
__device__ float g_part[512 * NCTA];
__device__ float g_scale[512];
__device__ float g_shift[512];

// ---------------- helpers ----------------
union F4U { float4 v; unsigned long long u[2]; float f[4]; };

__device__ __forceinline__ uint32_t smem_u32(const void* p) {
    uint32_t a;
    asm("{ .reg .u64 t; cvta.to.shared.u64 t, %1; cvt.u32.u64 %0, t; }" : "=r"(a) : "l"(p));
    return a;
}
__device__ __forceinline__ void cp4(uint32_t dst, const void* src) {
    asm volatile("cp.async.ca.shared.global [%0], [%1], 4;" :: "r"(dst), "l"(src));
}
__device__ __forceinline__ void cp16(uint32_t dst, const void* src) {
    asm volatile("cp.async.cg.shared.global [%0], [%1], 16;" :: "r"(dst), "l"(src));
}
#define CP_COMMIT() asm volatile("cp.async.commit_group;" ::: "memory")
#define CP_WAIT1()  asm volatile("cp.async.wait_group 1;" ::: "memory")
#define CP_WAIT0()  asm volatile("cp.async.wait_group 0;" ::: "memory")

__device__ __forceinline__ uint32_t pack_f2h(float lo, float hi) {
    __half2 h = __floats2half2_rn(lo, hi);     // .x (low bits) = lo
    return *reinterpret_cast<uint32_t*>(&h);
}

// D(16x8) += A(16x16,row) * B(16x8,col) ; f16 inputs, f32 accum
__device__ __forceinline__ void mma16(float* c, const uint32_t* a, const uint32_t* b) {
    asm volatile("mma.sync.aligned.m16n8k16.row.col.f32.f16.f16.f32 "
        "{%0,%1,%2,%3}, {%4,%5,%6,%7}, {%8,%9}, {%0,%1,%2,%3};"
        : "+f"(c[0]), "+f"(c[1]), "+f"(c[2]), "+f"(c[3])
        : "r"(a[0]), "r"(a[1]), "r"(a[2]), "r"(a[3]), "r"(b[0]), "r"(b[1]));
}

__device__ __forceinline__ unsigned long long pack2(float lo, float hi) {
    unsigned long long r;
    asm("mov.b64 %0, {%1, %2};" : "=l"(r) : "f"(lo), "f"(hi));
    return r;
}
__device__ __forceinline__ void unpack2(unsigned long long v, float& lo, float& hi) {
    asm("mov.b64 {%0, %1}, %2;" : "=f"(lo), "=f"(hi) : "l"(v));
}
__device__ __forceinline__ void fma2(unsigned long long& d, unsigned long long a, unsigned long long b) {
    asm("fma.rn.f32x2 %0, %1, %2, %3;" : "=l"(d) : "l"(a), "l"(b), "l"(d));
}

// accurate fast tanh: 1 - 2/(exp(2x)+1)  (abs err ~1e-7)
__device__ __forceinline__ float tanh_fast(float x) {
    float e;
    asm("ex2.approx.f32 %0, %1;" : "=f"(e) : "f"(x * 2.8853900817779268f));
    float r;
    asm("rcp.approx.f32 %0, %1;" : "=f"(r) : "f"(e + 1.0f));
    return fmaf(-2.0f, r, 1.0f);
}

// =====================================================================
// K0: g_wph = fp16(W + I), k-interleaved within each k16 block:
// order [0,1,8,9, 2,3,10,11, 4,5,12,13, 6,7,14,15]
// =====================================================================
__global__ void k0_prep(const float* __restrict__ fcw) {
    int i = blockIdx.x * 256 + threadIdx.x;
    if (i < 512 * 512) {
        int n = i >> 9, k = i & 511;
        float v = fcw[i] + (n == k ? 1.0f : 0.0f);
        int kk = k & 15;
        int pos = (k & ~15) + ((kk & 7) >> 1) * 4 + (kk & 1) + (((kk >> 3) & 1) << 1);
        g_wph[n * 512 + pos] = __float2half_rn(v);
    }
}

// =====================================================================
// K1: fp16 mma.sync GEMM (t = x@(W+I)^T + b) -> symmetric bilinear -> tanh
//     -> s (L2 evict_last) + BN partials. grid=1568, block=256 (2m x 4n warps)
// =====================================================================
__global__ void __launch_bounds__(256, 1)
k1_gemm_bilinear(const float* __restrict__ x, const float* __restrict__ fcb)
{
    extern __shared__ char sm[];
    float* smf = (float*)sm;
    const uint32_t smb = smem_u32(sm);
    const int tid = threadIdx.x;
    const int lid = tid & 31;
    const int wid = tid >> 5;
    const int wm = wid >> 2;            // 0..1
    const int wn = wid & 3;             // 0..3
    const int g  = lid >> 2;            // 0..7
    const int t4 = lid & 3;             // 0..3
    const int cta = blockIdx.x;
    const int n0 = cta * BM;

    // bias -> smem (region disjoint from stage buffers)
    smf[BIAS_OFF / 4 + tid] = fcb[tid];
    smf[BIAS_OFF / 4 + 256 + tid] = fcb[256 + tid];

    // ---- A loader coords ----
    const int klo = tid >> 6;           // 0..3
    const int ar = tid & 63;
    const int an = n0 + ar;
    const int ab_ = an / SPATIAL;
    const float* aptr = x + (size_t)ab_ * (512 * SPATIAL) + (an - ab_ * SPATIAL);

    auto loadA = [&](int kt, uint32_t st) {
        #pragma unroll
        for (int j = 0; j < 8; ++j)
            cp4(smb + st + (uint32_t)(ar * ASTRIDE + klo + 4 * j) * 4,
                aptr + (size_t)(kt * KC + klo + 4 * j) * SPATIAL);
    };
    auto loadB = [&](int kt, uint32_t st) {
        #pragma unroll
        for (int i = 0; i < 8; ++i) {
            int idx = i * 256 + tid;
            int n = idx >> 2, ch = idx & 3;
            cp16(smb + st + ABYTES + (uint32_t)(n * BSTRH * 2 + ch * 16),
                 g_wph + (size_t)n * 512 + kt * KC + ch * 8);
        }
    };

    loadA(0, 0); loadB(0, 0); CP_COMMIT();
    loadA(1, STAGEB); loadB(1, STAGEB); CP_COMMIT();

    float acc[2][16][4];
    #pragma unroll
    for (int a = 0; a < 2; ++a)
        #pragma unroll
        for (int b = 0; b < 16; ++b)
            #pragma unroll
            for (int c = 0; c < 4; ++c) acc[a][b][c] = 0.0f;

    for (int kt = 0; kt < NSTG; ++kt) {
        if (kt == NSTG - 1) { CP_WAIT0(); } else { CP_WAIT1(); }
        __syncthreads();
        const uint32_t stb = (kt & 1) * STAGEB;
        const float* As = (const float*)(sm + stb);
        const __half* Bs = (const __half*)(sm + stb + ABYTES);

        // A fragments (fp32 smem -> fp16 regs)
        uint32_t aa[2][2][4];
        #pragma unroll
        for (int mt = 0; mt < 2; ++mt) {
            const int r0 = wm * 32 + mt * 16 + g;
            #pragma unroll
            for (int ks = 0; ks < 2; ++ks) {
                const int c0 = ks * 16 + 2 * t4;
                float2 v00 = *(const float2*)(As + r0 * ASTRIDE + c0);
                float2 v10 = *(const float2*)(As + (r0 + 8) * ASTRIDE + c0);
                float2 v01 = *(const float2*)(As + r0 * ASTRIDE + c0 + 8);
                float2 v11 = *(const float2*)(As + (r0 + 8) * ASTRIDE + c0 + 8);
                aa[mt][ks][0] = pack_f2h(v00.x, v00.y);
                aa[mt][ks][1] = pack_f2h(v10.x, v10.y);
                aa[mt][ks][2] = pack_f2h(v01.x, v01.y);
                aa[mt][ks][3] = pack_f2h(v11.x, v11.y);
            }
        }
        #pragma unroll
        for (int ks = 0; ks < 2; ++ks) {
            uint32_t bf[16][2];
            #pragma unroll
            for (int nt = 0; nt < 16; ++nt) {
                uint2 bv = *(const uint2*)(Bs + (wn * 128 + nt * 8 + g) * BSTRH
                                              + ks * 16 + 4 * t4);
                bf[nt][0] = bv.x; bf[nt][1] = bv.y;
            }
            #pragma unroll
            for (int nt = 0; nt < 16; ++nt) {
                mma16(acc[0][nt], aa[0][ks], bf[nt]);
                mma16(acc[1][nt], aa[1][ks], bf[nt]);
            }
        }
        __syncthreads();
        if (kt + 2 < NSTG) {
            loadA(kt + 2, stb);
            loadB(kt + 2, stb);
            CP_COMMIT();
        }
    }

    // ---- write t' (+bias) to smem staging [64][520] ----
    float* ts = smf;
    const float* bias = smf + BIAS_OFF / 4;
    #pragma unroll
    for (int mt = 0; mt < 2; ++mt) {
        const int r = wm * 32 + mt * 16 + g;
        #pragma unroll
        for (int nt = 0; nt < 16; ++nt) {
            const int n = wn * 128 + nt * 8 + t4 * 2;
            const float b0 = bias[n], b1 = bias[n + 1];
            *(float2*)(ts + r * TS_STRIDE + n) =
                make_float2(acc[mt][nt][0] + b0, acc[mt][nt][1] + b1);
            *(float2*)(ts + (r + 8) * TS_STRIDE + n) =
                make_float2(acc[mt][nt][2] + b0, acc[mt][nt][3] + b1);
        }
    }
    __syncthreads();

    // ---- symmetric bilinear: s[p][q] = tanh( dot/32 ), only q >= (p&~1),
    //      mirrored to (q,p). Warp-uniform pp = wid>>1, row = (wid&1)*32+lid.
    float* sst = smf + SST_OFF / 4;
    {
        const int pp = wid >> 1;            // 0..3, uniform per warp
        const int r  = (wid & 1) * 32 + lid;
        const float* trow = ts + r * TS_STRIDE;

        if (pp < 2) {
            // variant A: p = pp + 4h, j0 = {0,2,4,6}, pairs {8,6,4,2} = 20
            unsigned long long sa[20];
            #pragma unroll
            for (int e = 0; e < 20; ++e) sa[e] = 0ull;
            for (int gg = 0; gg < 32; ++gg) {
                F4U q0, q1, q2, q3;
                q0.v = *(const float4*)(trow + gg * 16);
                q1.v = *(const float4*)(trow + gg * 16 + 4);
                q2.v = *(const float4*)(trow + gg * 16 + 8);
                q3.v = *(const float4*)(trow + gg * 16 + 12);
                unsigned long long pv[8] = {
                    q0.u[0], q0.u[1], q1.u[0], q1.u[1],
                    q2.u[0], q2.u[1], q3.u[0], q3.u[1] };
                float tp0 = (pp == 0) ? q0.f[0] : q0.f[1];
                float tp1 = (pp == 0) ? q1.f[0] : q1.f[1];
                float tp2 = (pp == 0) ? q2.f[0] : q2.f[1];
                float tp3 = (pp == 0) ? q3.f[0] : q3.f[1];
                unsigned long long t0 = pack2(tp0, tp0), t1 = pack2(tp1, tp1);
                unsigned long long t2 = pack2(tp2, tp2), t3 = pack2(tp3, tp3);
                fma2(sa[0], t0, pv[0]); fma2(sa[1], t0, pv[1]);
                fma2(sa[2], t0, pv[2]); fma2(sa[3], t0, pv[3]);
                fma2(sa[4], t0, pv[4]); fma2(sa[5], t0, pv[5]);
                fma2(sa[6], t0, pv[6]); fma2(sa[7], t0, pv[7]);
                fma2(sa[8], t1, pv[2]); fma2(sa[9], t1, pv[3]);
                fma2(sa[10], t1, pv[4]); fma2(sa[11], t1, pv[5]);
                fma2(sa[12], t1, pv[6]); fma2(sa[13], t1, pv[7]);
                fma2(sa[14], t2, pv[4]); fma2(sa[15], t2, pv[5]);
                fma2(sa[16], t2, pv[6]); fma2(sa[17], t2, pv[7]);
                fma2(sa[18], t3, pv[6]); fma2(sa[19], t3, pv[7]);
            }
            const int base[4] = {0, 8, 14, 18};
            const int j0h[4] = {0, 2, 4, 6};
            #pragma unroll
            for (int h = 0; h < 4; ++h) {
                const int p = pp + 4 * h;
                #pragma unroll
                for (int e = 0; e < 8; ++e) {
                    if (e + j0h[h] >= 8) break;
                    const int q = 2 * (j0h[h] + e);
                    float lo, hi;
                    unpack2(sa[base[h] + e], lo, hi);
                    float vlo = __half2float(__float2half_rn(tanh_fast(lo * 0.03125f)));
                    float vhi = __half2float(__float2half_rn(tanh_fast(hi * 0.03125f)));
                    sst[(p * 16 + q) * SST_STR + r]       = vlo;
                    sst[(p * 16 + q + 1) * SST_STR + r]   = vhi;
                    sst[(q * 16 + p) * SST_STR + r]       = vlo;
                    sst[((q + 1) * 16 + p) * SST_STR + r] = vhi;
                }
            }
        } else {
            // variant B: p = pp + 4h, j0 = {1,3,5,7}, pairs {7,5,3,1} = 16
            unsigned long long sa[16];
            #pragma unroll
            for (int e = 0; e < 16; ++e) sa[e] = 0ull;
            for (int gg = 0; gg < 32; ++gg) {
                F4U q0, q1, q2, q3;
                q0.v = *(const float4*)(trow + gg * 16);
                q1.v = *(const float4*)(trow + gg * 16 + 4);
                q2.v = *(const float4*)(trow + gg * 16 + 8);
                q3.v = *(const float4*)(trow + gg * 16 + 12);
                unsigned long long pv[8] = {
                    q0.u[0], q0.u[1], q1.u[0], q1.u[1],
                    q2.u[0], q2.u[1], q3.u[0], q3.u[1] };
                float tp0 = (pp == 2) ? q0.f[2] : q0.f[3];
                float tp1 = (pp == 2) ? q1.f[2] : q1.f[3];
                float tp2 = (pp == 2) ? q2.f[2] : q2.f[3];
                float tp3 = (pp == 2) ? q3.f[2] : q3.f[3];
                unsigned long long t0 = pack2(tp0, tp0), t1 = pack2(tp1, tp1);
                unsigned long long t2 = pack2(tp2, tp2), t3 = pack2(tp3, tp3);
                fma2(sa[0], t0, pv[1]); fma2(sa[1], t0, pv[2]);
                fma2(sa[2], t0, pv[3]); fma2(sa[3], t0, pv[4]);
                fma2(sa[4], t0, pv[5]); fma2(sa[5], t0, pv[6]);
                fma2(sa[6], t0, pv[7]);
                fma2(sa[7], t1, pv[3]); fma2(sa[8], t1, pv[4]);
                fma2(sa[9], t1, pv[5]); fma2(sa[10], t1, pv[6]);
                fma2(sa[11], t1, pv[7]);
                fma2(sa[12], t2, pv[5]); fma2(sa[13], t2, pv[6]);
                fma2(sa[14], t2, pv[7]);
                fma2(sa[15], t3, pv[7]);
            }
            const int base[4] = {0, 7, 12, 15};
            const int j0h[4] = {1, 3, 5, 7};
            #pragma unroll
            for (int h = 0; h < 4; ++h) {
                const int p = pp + 4 * h;
                #pragma unroll
                for (int e = 0; e < 7; ++e) {
                    if (e + j0h[h] >= 8) break;
                    const int q = 2 * (j0h[h] + e);
                    float lo, hi;
                    unpack2(sa[base[h] + e], lo, hi);
                    float vlo = __half2float(__float2half_rn(tanh_fast(lo * 0.03125f)));
                    float vhi = __half2float(__float2half_rn(tanh_fast(hi * 0.03125f)));
                    sst[(p * 16 + q) * SST_STR + r]       = vlo;
                    sst[(p * 16 + q + 1) * SST_STR + r]   = vhi;
                    sst[(q * 16 + p) * SST_STR + r]       = vlo;
                    sst[((q + 1) * 16 + p) * SST_STR + r] = vhi;
                }
            }
        }
    }
    __syncthreads();

    // ---- BN partials (thread = channel) ----
    {
        float s = 0.0f, q = 0.0f;
        const float* row = sst + tid * SST_STR;
        #pragma unroll
        for (int m4 = 0; m4 < 16; ++m4) {
            float4 v = *(const float4*)(row + m4 * 4);
            s += (v.x + v.y) + (v.z + v.w);
            q += fmaf(v.x, v.x, fmaf(v.y, v.y, fmaf(v.z, v.z, v.w * v.w)));
        }
        g_part[tid * NCTA + cta] = s;
        g_part[(tid + 256) * NCTA + cta] = q;
    }
    // ---- coalesced channel-major s write (fp16), L2 evict_last ----
    {
        unsigned long long pol;
        asm("createpolicy.fractional.L2::evict_last.b64 %0, 1.0;" : "=l"(pol));
        #pragma unroll
        for (int it = 0; it < 16; ++it) {
            int idx = it * 256 + tid;
            int ch = idx >> 4, c4 = idx & 15;
            float4 v = *(const float4*)(sst + ch * SST_STR + c4 * 4);
            __half2 h0 = __floats2half2_rn(v.x, v.y);
            __half2 h1 = __floats2half2_rn(v.z, v.w);
            uint32_t o0 = *reinterpret_cast<uint32_t*>(&h0);
            uint32_t o1 = *reinterpret_cast<uint32_t*>(&h1);
            __half* gp = g_sTh + (size_t)ch * TOTAL_N + n0 + c4 * 4;
            asm volatile("st.global.L2::cache_hint.v2.b32 [%0], {%1,%2}, %3;"
                         :: "l"(gp), "r"(o0), "r"(o1), "l"(pol) : "memory");
        }
    }
}

// =====================================================================
// K2: fold BN stats -> per-channel scale/shift (fp64 reduction)
// One block per s-channel cp; emits scale/shift for BOTH output channels
// 2cp and 2cp+1 (they share the same mean/var — identical reduction).
// =====================================================================
__global__ void k2_stats(const float* __restrict__ gamma,
                         const float* __restrict__ beta)
{
    __shared__ double rs[256], rq[256];
    const int cp = blockIdx.x;              // 0..255 (s channel)
    const int tid = threadIdx.x;
    double s = 0.0, q = 0.0;
    for (int i = tid; i < NCTA; i += 256) {
        s += (double)g_part[cp * NCTA + i];
        q += (double)g_part[(cp + 256) * NCTA + i];
    }
    rs[tid] = s; rq[tid] = q;
    __syncthreads();
    for (int off = 128; off > 0; off >>= 1) {
        if (tid < off) { rs[tid] += rs[tid + off]; rq[tid] += rq[tid + off]; }
        __syncthreads();
    }
    if (tid == 0) {
        const double inv_n = 1.0 / (double)TOTAL_N;
        const double mean = rs[0] * inv_n;
        const double var = rq[0] * inv_n - mean * mean;
        const double rstd = 1.0 / sqrt(var + 1e-5);
        const int c0 = cp * 2;
        #pragma unroll
        for (int j = 0; j < 2; ++j) {
            const double gm = (double)gamma[c0 + j];
            g_scale[c0 + j] = (float)(gm * rstd);
            g_shift[c0 + j] = (float)((double)beta[c0 + j] - mean * rstd * gm);
        }
    }
}

// =====================================================================
// K3: out = x + s[c>>1]*scale[c] + shift[c]
// One thread = one channel-PAIR (2c, 2c+1) x 4 spatial: s read once
// (streaming ld, hits the evict_last L2 lines), x streaming, out streaming.
// =====================================================================
__global__ void k3_out(const float* __restrict__ x, float* __restrict__ out)
{
    const int idx = blockIdx.x * 256 + threadIdx.x;
    if (idx >= TOTAL_OUT / 8) return;          // 6,422,528 threads
    const int sp4 = idx % 784;                 // SPATIAL/4
    const int rest = idx / 784;
    const int cp = rest & 255;                 // s channel (c>>1)
    const int b = rest >> 8;
    const int c0 = cp * 2;

    uint2 raw = __ldcs((const uint2*)(g_sTh + (size_t)cp * TOTAL_N + b * SPATIAL + sp4 * 4));
    __half2 h0 = *reinterpret_cast<__half2*>(&raw.x);
    __half2 h1 = *reinterpret_cast<__half2*>(&raw.y);
    float2 f0 = __half22float2(h0);
    float2 f1 = __half22float2(h1);

    const float* xp = x + ((size_t)(b * 512 + c0)) * SPATIAL + sp4 * 4;
    float4 xv0 = __ldcs((const float4*)xp);
    float4 xv1 = __ldcs((const float4*)(xp + SPATIAL));

    const float sc0 = g_scale[c0],     sh0 = g_shift[c0];
    const float sc1 = g_scale[c0 + 1], sh1 = g_shift[c0 + 1];

    float4 o0, o1;
    o0.x = xv0.x + fmaf(f0.x, sc0, sh0);
    o0.y = xv0.y + fmaf(f0.y, sc0, sh0);
    o0.z = xv0.z + fmaf(f1.x, sc0, sh0);
    o0.w = xv0.w + fmaf(f1.y, sc0, sh0);
    o1.x = xv1.x + fmaf(f0.x, sc1, sh1);
    o1.y = xv1.y + fmaf(f0.y, sc1, sh1);
    o1.z = xv1.z + fmaf(f1.x, sc1, sh1);
    o1.w = xv1.w + fmaf(f1.y, sc1, sh1);

    float* op = out + ((size_t)(b * 512 + c0)) * SPATIAL + sp4 * 4;
    __stcs((float4*)op, o0);
    __stcs((float4*)(op + SPATIAL), o1);
}

// =====================================================================
extern "C" void kernel_launch(void* const* d_in, const int* in_sizes, int n_in,
                              void* d_out, int out_size)
{
    const float* x     = (const float*)d_in[0];
    const float* fcw   = (const float*)d_in[1];
    const float* fcb   = (const float*)d_in[2];
    const float* gamma = (const float*)d_in[3];
    const float* beta  = (const float*)d_in[4];
    float* out = (float*)d_out;

    cudaFuncSetAttribute(k1_gemm_bilinear,
                         cudaFuncAttributeMaxDynamicSharedMemorySize, SMEM_BYTES);

    k0_prep<<<1024, 256>>>(fcw);
    k1_gemm_bilinear<<<NCTA, 256, SMEM_BYTES>>>(x, fcb);
    k2_stats<<<256, 256>>>(gamma, beta);
    k3_out<<<(TOTAL_OUT / 8 + 255) / 256, 256>>>(x, out);
}

// round 17
// speedup vs baseline: 1.0358x; 1.0106x over previous
#include <cuda_runtime.h>
#include <cuda_fp16.h>
#include <cstdint>

// ---------------- problem constants ----------------
#define SPATIAL   3136
#define TOTAL_N   100352
#define BM        64
#define NCTA      1568                // TOTAL_N / BM
#define KC        32
#define NSTG      16                  // 512 / 32
#define ASTRIDE   40                  // padded floats per A smem row
#define BSTRH     48                  // padded halves per B smem row
#define ABYTES    (64 * ASTRIDE * 4)      // 10240
#define BBYTES    (512 * BSTRH * 2)       // 49152
#define STAGEB    (ABYTES + BBYTES)       // 59392
#define TS_STRIDE 520
#define SST_OFF   133120              // 64*520*4
#define SST_STR   68
#define BIAS_OFF  202752              // SST_OFF + 256*68*4
#define SMEM_BYTES 204800
#define TOTAL_OUT (32 * 512 * SPATIAL)

// ---------------- device scratch ----------------
__device__ __half g_wph[512 * 512];        // (W + I) fp16, k-interleaved per 16-chunk
__device__ __half g_sTh[256u * 100352u];   // s channel-major [256][N], fp16
__device__ float g_part[NCTA * 512];       // [cta][ch(0..255)=sum, ch(256..511)=sumsq]
__device__ float g_scale[512];
__device__ float g_shift[512];

// ---------------- helpers ----------------
union F4U { float4 v; unsigned long long u[2]; float f[4]; };

__device__ __forceinline__ uint32_t smem_u32(const void* p) {
    uint32_t a;
    asm("{ .reg .u64 t; cvta.to.shared.u64 t, %1; cvt.u32.u64 %0, t; }" : "=r"(a) : "l"(p));
    return a;
}
__device__ __forceinline__ void cp4(uint32_t dst, const void* src) {
    asm volatile("cp.async.ca.shared.global [%0], [%1], 4;" :: "r"(dst), "l"(src));
}
__device__ __forceinline__ void cp16(uint32_t dst, const void* src) {
    asm volatile("cp.async.cg.shared.global [%0], [%1], 16;" :: "r"(dst), "l"(src));
}
#define CP_COMMIT() asm volatile("cp.async.commit_group;" ::: "memory")
#define CP_WAIT1()  asm volatile("cp.async.wait_group 1;" ::: "memory")
#define CP_WAIT0()  asm volatile("cp.async.wait_group 0;" ::: "memory")

__device__ __forceinline__ uint32_t pack_f2h(float lo, float hi) {
    __half2 h = __floats2half2_rn(lo, hi);     // .x (low bits) = lo
    return *reinterpret_cast<uint32_t*>(&h);
}

// D(16x8) += A(16x16,row) * B(16x8,col) ; f16 inputs, f32 accum
__device__ __forceinline__ void mma16(float* c, const uint32_t* a, const uint32_t* b) {
    asm volatile("mma.sync.aligned.m16n8k16.row.col.f32.f16.f16.f32 "
        "{%0,%1,%2,%3}, {%4,%5,%6,%7}, {%8,%9}, {%0,%1,%2,%3};"
        : "+f"(c[0]), "+f"(c[1]), "+f"(c[2]), "+f"(c[3])
        : "r"(a[0]), "r"(a[1]), "r"(a[2]), "r"(a[3]), "r"(b[0]), "r"(b[1]));
}

__device__ __forceinline__ unsigned long long pack2(float lo, float hi) {
    unsigned long long r;
    asm("mov.b64 %0, {%1, %2};" : "=l"(r) : "f"(lo), "f"(hi));
    return r;
}
__device__ __forceinline__ void unpack2(unsigned long long v, float& lo, float& hi) {
    asm("mov.b64 {%0, %1}, %2;" : "=f"(lo), "=f"(hi) : "l"(v));
}
__device__ __forceinline__ void fma2(unsigned long long& d, unsigned long long a, unsigned long long b) {
    asm("fma.rn.f32x2 %0, %1, %2, %3;" : "=l"(d) : "l"(a), "l"(b), "l"(d));
}

// accurate fast tanh: 1 - 2/(exp(2x)+1)  (abs err ~1e-7)
__device__ __forceinline__ float tanh_fast(float x) {
    float e;
    asm("ex2.approx.f32 %0, %1;" : "=f"(e) : "f"(x * 2.8853900817779268f));
    float r;
    asm("rcp.approx.f32 %0, %1;" : "=f"(r) : "f"(e + 1.0f));
    return fmaf(-2.0f, r, 1.0f);
}

// =====================================================================
// K0: g_wph = fp16(W + I), k-interleaved within each k16 block:
// order [0,1,8,9, 2,3,10,11, 4,5,12,13, 6,7,14,15]
// =====================================================================
__global__ void k0_prep(const float* __restrict__ fcw) {
    int i = blockIdx.x * 256 + threadIdx.x;
    if (i < 512 * 512) {
        int n = i >> 9, k = i & 511;
        float v = fcw[i] + (n == k ? 1.0f : 0.0f);
        int kk = k & 15;
        int pos = (k & ~15) + ((kk & 7) >> 1) * 4 + (kk & 1) + (((kk >> 3) & 1) << 1);
        g_wph[n * 512 + pos] = __float2half_rn(v);
    }
}

// =====================================================================
// K1: fp16 mma.sync GEMM (t = x@(W+I)^T + b) -> symmetric bilinear -> tanh
//     -> s (L2 evict_last) + BN partials (coalesced per-CTA rows).
// grid=1568, block=256 (2m x 4n warps)
// =====================================================================
__global__ void __launch_bounds__(256, 1)
k1_gemm_bilinear(const float* __restrict__ x, const float* __restrict__ fcb)
{
    extern __shared__ char sm[];
    float* smf = (float*)sm;
    const uint32_t smb = smem_u32(sm);
    const int tid = threadIdx.x;
    const int lid = tid & 31;
    const int wid = tid >> 5;
    const int wm = wid >> 2;            // 0..1
    const int wn = wid & 3;             // 0..3
    const int g  = lid >> 2;            // 0..7
    const int t4 = lid & 3;             // 0..3
    const int cta = blockIdx.x;
    const int n0 = cta * BM;

    // bias -> smem (region disjoint from stage buffers)
    smf[BIAS_OFF / 4 + tid] = fcb[tid];
    smf[BIAS_OFF / 4 + 256 + tid] = fcb[256 + tid];

    // ---- A loader coords ----
    const int klo = tid >> 6;           // 0..3
    const int ar = tid & 63;
    const int an = n0 + ar;
    const int ab_ = an / SPATIAL;
    const float* aptr = x + (size_t)ab_ * (512 * SPATIAL) + (an - ab_ * SPATIAL);

    auto loadA = [&](int kt, uint32_t st) {
        #pragma unroll
        for (int j = 0; j < 8; ++j)
            cp4(smb + st + (uint32_t)(ar * ASTRIDE + klo + 4 * j) * 4,
                aptr + (size_t)(kt * KC + klo + 4 * j) * SPATIAL);
    };
    auto loadB = [&](int kt, uint32_t st) {
        #pragma unroll
        for (int i = 0; i < 8; ++i) {
            int idx = i * 256 + tid;
            int n = idx >> 2, ch = idx & 3;
            cp16(smb + st + ABYTES + (uint32_t)(n * BSTRH * 2 + ch * 16),
                 g_wph + (size_t)n * 512 + kt * KC + ch * 8);
        }
    };

    loadA(0, 0); loadB(0, 0); CP_COMMIT();
    loadA(1, STAGEB); loadB(1, STAGEB); CP_COMMIT();

    float acc[2][16][4];
    #pragma unroll
    for (int a = 0; a < 2; ++a)
        #pragma unroll
        for (int b = 0; b < 16; ++b)
            #pragma unroll
            for (int c = 0; c < 4; ++c) acc[a][b][c] = 0.0f;

    for (int kt = 0; kt < NSTG; ++kt) {
        if (kt == NSTG - 1) { CP_WAIT0(); } else { CP_WAIT1(); }
        __syncthreads();
        const uint32_t stb = (kt & 1) * STAGEB;
        const float* As = (const float*)(sm + stb);
        const __half* Bs = (const __half*)(sm + stb + ABYTES);

        // A fragments (fp32 smem -> fp16 regs)
        uint32_t aa[2][2][4];
        #pragma unroll
        for (int mt = 0; mt < 2; ++mt) {
            const int r0 = wm * 32 + mt * 16 + g;
            #pragma unroll
            for (int ks = 0; ks < 2; ++ks) {
                const int c0 = ks * 16 + 2 * t4;
                float2 v00 = *(const float2*)(As + r0 * ASTRIDE + c0);
                float2 v10 = *(const float2*)(As + (r0 + 8) * ASTRIDE + c0);
                float2 v01 = *(const float2*)(As + r0 * ASTRIDE + c0 + 8);
                float2 v11 = *(const float2*)(As + (r0 + 8) * ASTRIDE + c0 + 8);
                aa[mt][ks][0] = pack_f2h(v00.x, v00.y);
                aa[mt][ks][1] = pack_f2h(v10.x, v10.y);
                aa[mt][ks][2] = pack_f2h(v01.x, v01.y);
                aa[mt][ks][3] = pack_f2h(v11.x, v11.y);
            }
        }
        #pragma unroll
        for (int ks = 0; ks < 2; ++ks) {
            uint32_t bf[16][2];
            #pragma unroll
            for (int nt = 0; nt < 16; ++nt) {
                uint2 bv = *(const uint2*)(Bs + (wn * 128 + nt * 8 + g) * BSTRH
                                              + ks * 16 + 4 * t4);
                bf[nt][0] = bv.x; bf[nt][1] = bv.y;
            }
            #pragma unroll
            for (int nt = 0; nt < 16; ++nt) {
                mma16(acc[0][nt], aa[0][ks], bf[nt]);
                mma16(acc[1][nt], aa[1][ks], bf[nt]);
            }
        }
        __syncthreads();
        if (kt + 2 < NSTG) {
            loadA(kt + 2, stb);
            loadB(kt + 2, stb);
            CP_COMMIT();
        }
    }

    // ---- write t' (+bias) to smem staging [64][520] ----
    float* ts = smf;
    const float* bias = smf + BIAS_OFF / 4;
    #pragma unroll
    for (int mt = 0; mt < 2; ++mt) {
        const int r = wm * 32 + mt * 16 + g;
        #pragma unroll
        for (int nt = 0; nt < 16; ++nt) {
            const int n = wn * 128 + nt * 8 + t4 * 2;
            const float b0 = bias[n], b1 = bias[n + 1];
            *(float2*)(ts + r * TS_STRIDE + n) =
                make_float2(acc[mt][nt][0] + b0, acc[mt][nt][1] + b1);
            *(float2*)(ts + (r + 8) * TS_STRIDE + n) =
                make_float2(acc[mt][nt][2] + b0, acc[mt][nt][3] + b1);
        }
    }
    __syncthreads();

    // ---- symmetric bilinear: s[p][q] = tanh( dot/32 ), only q >= (p&~1),
    //      mirrored to (q,p). Warp-uniform pp = wid>>1, row = (wid&1)*32+lid.
    float* sst = smf + SST_OFF / 4;
    {
        const int pp = wid >> 1;            // 0..3, uniform per warp
        const int r  = (wid & 1) * 32 + lid;
        const float* trow = ts + r * TS_STRIDE;

        if (pp < 2) {
            // variant A: p = pp + 4h, j0 = {0,2,4,6}, pairs {8,6,4,2} = 20
            unsigned long long sa[20];
            #pragma unroll
            for (int e = 0; e < 20; ++e) sa[e] = 0ull;
            for (int gg = 0; gg < 32; ++gg) {
                F4U q0, q1, q2, q3;
                q0.v = *(const float4*)(trow + gg * 16);
                q1.v = *(const float4*)(trow + gg * 16 + 4);
                q2.v = *(const float4*)(trow + gg * 16 + 8);
                q3.v = *(const float4*)(trow + gg * 16 + 12);
                unsigned long long pv[8] = {
                    q0.u[0], q0.u[1], q1.u[0], q1.u[1],
                    q2.u[0], q2.u[1], q3.u[0], q3.u[1] };
                float tp0 = (pp == 0) ? q0.f[0] : q0.f[1];
                float tp1 = (pp == 0) ? q1.f[0] : q1.f[1];
                float tp2 = (pp == 0) ? q2.f[0] : q2.f[1];
                float tp3 = (pp == 0) ? q3.f[0] : q3.f[1];
                unsigned long long t0 = pack2(tp0, tp0), t1 = pack2(tp1, tp1);
                unsigned long long t2 = pack2(tp2, tp2), t3 = pack2(tp3, tp3);
                fma2(sa[0], t0, pv[0]); fma2(sa[1], t0, pv[1]);
                fma2(sa[2], t0, pv[2]); fma2(sa[3], t0, pv[3]);
                fma2(sa[4], t0, pv[4]); fma2(sa[5], t0, pv[5]);
                fma2(sa[6], t0, pv[6]); fma2(sa[7], t0, pv[7]);
                fma2(sa[8], t1, pv[2]); fma2(sa[9], t1, pv[3]);
                fma2(sa[10], t1, pv[4]); fma2(sa[11], t1, pv[5]);
                fma2(sa[12], t1, pv[6]); fma2(sa[13], t1, pv[7]);
                fma2(sa[14], t2, pv[4]); fma2(sa[15], t2, pv[5]);
                fma2(sa[16], t2, pv[6]); fma2(sa[17], t2, pv[7]);
                fma2(sa[18], t3, pv[6]); fma2(sa[19], t3, pv[7]);
            }
            const int base[4] = {0, 8, 14, 18};
            const int j0h[4] = {0, 2, 4, 6};
            #pragma unroll
            for (int h = 0; h < 4; ++h) {
                const int p = pp + 4 * h;
                #pragma unroll
                for (int e = 0; e < 8; ++e) {
                    if (e + j0h[h] >= 8) break;
                    const int q = 2 * (j0h[h] + e);
                    float lo, hi;
                    unpack2(sa[base[h] + e], lo, hi);
                    float vlo = __half2float(__float2half_rn(tanh_fast(lo * 0.03125f)));
                    float vhi = __half2float(__float2half_rn(tanh_fast(hi * 0.03125f)));
                    sst[(p * 16 + q) * SST_STR + r]       = vlo;
                    sst[(p * 16 + q + 1) * SST_STR + r]   = vhi;
                    sst[(q * 16 + p) * SST_STR + r]       = vlo;
                    sst[((q + 1) * 16 + p) * SST_STR + r] = vhi;
                }
            }
        } else {
            // variant B: p = pp + 4h, j0 = {1,3,5,7}, pairs {7,5,3,1} = 16
            unsigned long long sa[16];
            #pragma unroll
            for (int e = 0; e < 16; ++e) sa[e] = 0ull;
            for (int gg = 0; gg < 32; ++gg) {
                F4U q0, q1, q2, q3;
                q0.v = *(const float4*)(trow + gg * 16);
                q1.v = *(const float4*)(trow + gg * 16 + 4);
                q2.v = *(const float4*)(trow + gg * 16 + 8);
                q3.v = *(const float4*)(trow + gg * 16 + 12);
                unsigned long long pv[8] = {
                    q0.u[0], q0.u[1], q1.u[0], q1.u[1],
                    q2.u[0], q2.u[1], q3.u[0], q3.u[1] };
                float tp0 = (pp == 2) ? q0.f[2] : q0.f[3];
                float tp1 = (pp == 2) ? q1.f[2] : q1.f[3];
                float tp2 = (pp == 2) ? q2.f[2] : q2.f[3];
                float tp3 = (pp == 2) ? q3.f[2] : q3.f[3];
                unsigned long long t0 = pack2(tp0, tp0), t1 = pack2(tp1, tp1);
                unsigned long long t2 = pack2(tp2, tp2), t3 = pack2(tp3, tp3);
                fma2(sa[0], t0, pv[1]); fma2(sa[1], t0, pv[2]);
                fma2(sa[2], t0, pv[3]); fma2(sa[3], t0, pv[4]);
                fma2(sa[4], t0, pv[5]); fma2(sa[5], t0, pv[6]);
                fma2(sa[6], t0, pv[7]);
                fma2(sa[7], t1, pv[3]); fma2(sa[8], t1, pv[4]);
                fma2(sa[9], t1, pv[5]); fma2(sa[10], t1, pv[6]);
                fma2(sa[11], t1, pv[7]);
                fma2(sa[12], t2, pv[5]); fma2(sa[13], t2, pv[6]);
                fma2(sa[14], t2, pv[7]);
                fma2(sa[15], t3, pv[7]);
            }
            const int base[4] = {0, 7, 12, 15};
            const int j0h[4] = {1, 3, 5, 7};
            #pragma unroll
            for (int h = 0; h < 4; ++h) {
                const int p = pp + 4 * h;
                #pragma unroll
                for (int e = 0; e < 7; ++e) {
                    if (e + j0h[h] >= 8) break;
                    const int q = 2 * (j0h[h] + e);
                    float lo, hi;
                    unpack2(sa[base[h] + e], lo, hi);
                    float vlo = __half2float(__float2half_rn(tanh_fast(lo * 0.03125f)));
                    float vhi = __half2float(__float2half_rn(tanh_fast(hi * 0.03125f)));
                    sst[(p * 16 + q) * SST_STR + r]       = vlo;
                    sst[(p * 16 + q + 1) * SST_STR + r]   = vhi;
                    sst[(q * 16 + p) * SST_STR + r]       = vlo;
                    sst[((q + 1) * 16 + p) * SST_STR + r] = vhi;
                }
            }
        }
    }
    __syncthreads();

    // ---- BN partials (thread = channel), coalesced per-CTA row ----
    {
        float s = 0.0f, q = 0.0f;
        const float* row = sst + tid * SST_STR;
        #pragma unroll
        for (int m4 = 0; m4 < 16; ++m4) {
            float4 v = *(const float4*)(row + m4 * 4);
            s += (v.x + v.y) + (v.z + v.w);
            q += fmaf(v.x, v.x, fmaf(v.y, v.y, fmaf(v.z, v.z, v.w * v.w)));
        }
        g_part[(size_t)cta * 512 + tid]       = s;
        g_part[(size_t)cta * 512 + 256 + tid] = q;
    }
    // ---- coalesced channel-major s write (fp16), L2 evict_last ----
    {
        unsigned long long pol;
        asm("createpolicy.fractional.L2::evict_last.b64 %0, 1.0;" : "=l"(pol));
        #pragma unroll
        for (int it = 0; it < 16; ++it) {
            int idx = it * 256 + tid;
            int ch = idx >> 4, c4 = idx & 15;
            float4 v = *(const float4*)(sst + ch * SST_STR + c4 * 4);
            __half2 h0 = __floats2half2_rn(v.x, v.y);
            __half2 h1 = __floats2half2_rn(v.z, v.w);
            uint32_t o0 = *reinterpret_cast<uint32_t*>(&h0);
            uint32_t o1 = *reinterpret_cast<uint32_t*>(&h1);
            __half* gp = g_sTh + (size_t)ch * TOTAL_N + n0 + c4 * 4;
            asm volatile("st.global.L2::cache_hint.v2.b32 [%0], {%1,%2}, %3;"
                         :: "l"(gp), "r"(o0), "r"(o1), "l"(pol) : "memory");
        }
    }
}

// =====================================================================
// K2: fold BN stats -> per-channel scale/shift (fp64 reduction)
// One block per s-channel cp; reads g_part[i*512 + cp] (strided but tiny);
// emits scale/shift for BOTH output channels 2cp, 2cp+1.
// =====================================================================
__global__ void k2_stats(const float* __restrict__ gamma,
                         const float* __restrict__ beta)
{
    __shared__ double rs[256], rq[256];
    const int cp = blockIdx.x;              // 0..255 (s channel)
    const int tid = threadIdx.x;
    double s = 0.0, q = 0.0;
    for (int i = tid; i < NCTA; i += 256) {
        s += (double)g_part[(size_t)i * 512 + cp];
        q += (double)g_part[(size_t)i * 512 + 256 + cp];
    }
    rs[tid] = s; rq[tid] = q;
    __syncthreads();
    for (int off = 128; off > 0; off >>= 1) {
        if (tid < off) { rs[tid] += rs[tid + off]; rq[tid] += rq[tid + off]; }
        __syncthreads();
    }
    if (tid == 0) {
        const double inv_n = 1.0 / (double)TOTAL_N;
        const double mean = rs[0] * inv_n;
        const double var = rq[0] * inv_n - mean * mean;
        const double rstd = 1.0 / sqrt(var + 1e-5);
        const int c0 = cp * 2;
        #pragma unroll
        for (int j = 0; j < 2; ++j) {
            const double gm = (double)gamma[c0 + j];
            g_scale[c0 + j] = (float)(gm * rstd);
            g_shift[c0 + j] = (float)((double)beta[c0 + j] - mean * rstd * gm);
        }
    }
}

// =====================================================================
// K3: out = x + s[c>>1]*scale[c] + shift[c]
// One thread = one channel-PAIR (2c, 2c+1) x 4 spatial: s read once
// (streaming ld, hits the evict_last L2 lines), x streaming, out streaming.
// =====================================================================
__global__ void k3_out(const float* __restrict__ x, float* __restrict__ out)
{
    const int idx = blockIdx.x * 256 + threadIdx.x;
    if (idx >= TOTAL_OUT / 8) return;          // 6,422,528 threads
    const int sp4 = idx % 784;                 // SPATIAL/4
    const int rest = idx / 784;
    const int cp = rest & 255;                 // s channel (c>>1)
    const int b = rest >> 8;
    const int c0 = cp * 2;

    uint2 raw = __ldcs((const uint2*)(g_sTh + (size_t)cp * TOTAL_N + b * SPATIAL + sp4 * 4));
    __half2 h0 = *reinterpret_cast<__half2*>(&raw.x);
    __half2 h1 = *reinterpret_cast<__half2*>(&raw.y);
    float2 f0 = __half22float2(h0);
    float2 f1 = __half22float2(h1);

    const float* xp = x + ((size_t)(b * 512 + c0)) * SPATIAL + sp4 * 4;
    float4 xv0 = __ldcs((const float4*)xp);
    float4 xv1 = __ldcs((const float4*)(xp + SPATIAL));

    const float sc0 = g_scale[c0],     sh0 = g_shift[c0];
    const float sc1 = g_scale[c0 + 1], sh1 = g_shift[c0 + 1];

    float4 o0, o1;
    o0.x = xv0.x + fmaf(f0.x, sc0, sh0);
    o0.y = xv0.y + fmaf(f0.y, sc0, sh0);
    o0.z = xv0.z + fmaf(f1.x, sc0, sh0);
    o0.w = xv0.w + fmaf(f1.y, sc0, sh0);
    o1.x = xv1.x + fmaf(f0.x, sc1, sh1);
    o1.y = xv1.y + fmaf(f0.y, sc1, sh1);
    o1.z = xv1.z + fmaf(f1.x, sc1, sh1);
    o1.w = xv1.w + fmaf(f1.y, sc1, sh1);

    float* op = out + ((size_t)(b * 512 + c0)) * SPATIAL + sp4 * 4;
    __stcs((float4*)op, o0);
    __stcs((float4*)(op + SPATIAL), o1);
}

// =====================================================================
extern "C" void kernel_launch(void* const* d_in, const int* in_sizes, int n_in,
                              void* d_out, int out_size)
{
    const float* x     = (const float*)d_in[0];
    const float* fcw   = (const float*)d_in[1];
    const float* fcb   = (const float*)d_in[2];
    const float* gamma = (const float*)d_in[3];
    const float* beta  = (const float*)d_in[4];
    float* out = (float*)d_out;

    cudaFuncSetAttribute(k1_gemm_bilinear,
                         cudaFuncAttributeMaxDynamicSharedMemorySize, SMEM_BYTES);

    k0_prep<<<1024, 256>>>(fcw);
    k1_gemm_bilinear<<<NCTA, 256, SMEM_BYTES>>>(x, fcb);
    k2_stats<<<256, 256>>>(gamma, beta);
    k3_out<<<(TOTAL_OUT / 8 + 255) / 256, 256>>>(x, out);
}